// round 1
// baseline (speedup 1.0000x reference)
#include <cuda_runtime.h>

#define BB 8
#define SS 2048
#define DD 512
#define NEGV -1000000000.0f

// Scratch (device globals are the sanctioned scratch mechanism)
__device__ float g_q[BB * SS * DD];
__device__ float g_k[BB * SS * DD];
__device__ float g_v[BB * SS * DD];
__device__ float g_p[(size_t)BB * SS * SS];

// ---------------------------------------------------------------------------
// Kernel 1: fused QKV projection.  out[n,e] = sum_d x[n,d] * W[e,d] + bias[e]
// NT gemm (both operands K-contiguous). 128x128 tile, BK=16, 8x8 microtile.
// grid: (DD/128, (BB*SS)/128, 3)
// ---------------------------------------------------------------------------
__global__ __launch_bounds__(256) void qkv_gemm(
    const float* __restrict__ x,
    const float* __restrict__ Wq, const float* __restrict__ bq,
    const float* __restrict__ Wk, const float* __restrict__ bk,
    const float* __restrict__ Wv, const float* __restrict__ bv)
{
    const float* W; const float* bias; float* out;
    int z = blockIdx.z;
    if (z == 0)      { W = Wq; bias = bq; out = g_q; }
    else if (z == 1) { W = Wk; bias = bk; out = g_k; }
    else             { W = Wv; bias = bv; out = g_v; }

    __shared__ float As[16][132];
    __shared__ float Bs[16][132];

    int tid = threadIdx.x;
    int n0 = blockIdx.y * 128;
    int e0 = blockIdx.x * 128;

    int lr = tid >> 2;          // 0..63
    int lc = (tid & 3) * 4;     // 0,4,8,12
    int ty = tid >> 4, tx = tid & 15;

    const float* Aptr = x + (size_t)n0 * DD;
    const float* Bptr = W + (size_t)e0 * DD;

    float acc[8][8] = {};

    for (int k0 = 0; k0 < DD; k0 += 16) {
#pragma unroll
        for (int h = 0; h < 2; h++) {
            int row = lr + h * 64;
            float4 a = *(const float4*)(Aptr + (size_t)row * DD + k0 + lc);
            As[lc + 0][row] = a.x; As[lc + 1][row] = a.y;
            As[lc + 2][row] = a.z; As[lc + 3][row] = a.w;
            float4 b = *(const float4*)(Bptr + (size_t)row * DD + k0 + lc);
            Bs[lc + 0][row] = b.x; Bs[lc + 1][row] = b.y;
            Bs[lc + 2][row] = b.z; Bs[lc + 3][row] = b.w;
        }
        __syncthreads();
#pragma unroll
        for (int kk = 0; kk < 16; kk++) {
            float a[8], b[8];
            *(float4*)&a[0] = *(const float4*)&As[kk][ty * 8];
            *(float4*)&a[4] = *(const float4*)&As[kk][ty * 8 + 4];
            *(float4*)&b[0] = *(const float4*)&Bs[kk][tx * 8];
            *(float4*)&b[4] = *(const float4*)&Bs[kk][tx * 8 + 4];
#pragma unroll
            for (int i = 0; i < 8; i++)
#pragma unroll
                for (int j = 0; j < 8; j++)
                    acc[i][j] += a[i] * b[j];
        }
        __syncthreads();
    }

#pragma unroll
    for (int i = 0; i < 8; i++) {
        int n = n0 + ty * 8 + i;
#pragma unroll
        for (int j = 0; j < 8; j += 4) {
            int e = e0 + tx * 8 + j;
            float4 r;
            r.x = acc[i][j + 0] + bias[e + 0];
            r.y = acc[i][j + 1] + bias[e + 1];
            r.z = acc[i][j + 2] + bias[e + 2];
            r.w = acc[i][j + 3] + bias[e + 3];
            *(float4*)(out + (size_t)n * DD + e) = r;
        }
    }
}

// ---------------------------------------------------------------------------
// Kernel 2: scores[b,q,k] = mask ? (q.k)*scale : NEG.
// Tiles entirely outside the valid region skip the K-loop (exact).
// grid: (SS/128, SS/128, BB)
// ---------------------------------------------------------------------------
__global__ __launch_bounds__(256) void scores_gemm(const int* __restrict__ ev)
{
    int b = blockIdx.z;
    int q0 = blockIdx.y * 128;
    int k0 = blockIdx.x * 128;
    int L = ev[b];

    int tid = threadIdx.x;
    int ty = tid >> 4, tx = tid & 15;
    float* outp = g_p + (size_t)b * SS * SS;

    if (q0 >= L || k0 >= L) {
        float4 neg = make_float4(NEGV, NEGV, NEGV, NEGV);
#pragma unroll
        for (int i = 0; i < 8; i++) {
            int q = q0 + ty * 8 + i;
            *(float4*)(outp + (size_t)q * SS + k0 + tx * 8)     = neg;
            *(float4*)(outp + (size_t)q * SS + k0 + tx * 8 + 4) = neg;
        }
        return;
    }

    __shared__ float As[16][132];
    __shared__ float Bs[16][132];

    int lr = tid >> 2;
    int lc = (tid & 3) * 4;

    const float* Aptr = g_q + (size_t)b * SS * DD + (size_t)q0 * DD;
    const float* Bptr = g_k + (size_t)b * SS * DD + (size_t)k0 * DD;

    float acc[8][8] = {};

    for (int c0 = 0; c0 < DD; c0 += 16) {
#pragma unroll
        for (int h = 0; h < 2; h++) {
            int row = lr + h * 64;
            float4 a = *(const float4*)(Aptr + (size_t)row * DD + c0 + lc);
            As[lc + 0][row] = a.x; As[lc + 1][row] = a.y;
            As[lc + 2][row] = a.z; As[lc + 3][row] = a.w;
            float4 bvv = *(const float4*)(Bptr + (size_t)row * DD + c0 + lc);
            Bs[lc + 0][row] = bvv.x; Bs[lc + 1][row] = bvv.y;
            Bs[lc + 2][row] = bvv.z; Bs[lc + 3][row] = bvv.w;
        }
        __syncthreads();
#pragma unroll
        for (int kk = 0; kk < 16; kk++) {
            float a[8], bb[8];
            *(float4*)&a[0]  = *(const float4*)&As[kk][ty * 8];
            *(float4*)&a[4]  = *(const float4*)&As[kk][ty * 8 + 4];
            *(float4*)&bb[0] = *(const float4*)&Bs[kk][tx * 8];
            *(float4*)&bb[4] = *(const float4*)&Bs[kk][tx * 8 + 4];
#pragma unroll
            for (int i = 0; i < 8; i++)
#pragma unroll
                for (int j = 0; j < 8; j++)
                    acc[i][j] += a[i] * bb[j];
        }
        __syncthreads();
    }

    const float scale = 0.0441941738241592f;  // 1/sqrt(512)
#pragma unroll
    for (int i = 0; i < 8; i++) {
        int q = q0 + ty * 8 + i;
        bool qok = (q < L);
#pragma unroll
        for (int j = 0; j < 8; j += 4) {
            int k = k0 + tx * 8 + j;
            float4 r;
            r.x = (qok && (k + 0) < L) ? acc[i][j + 0] * scale : NEGV;
            r.y = (qok && (k + 1) < L) ? acc[i][j + 1] * scale : NEGV;
            r.z = (qok && (k + 2) < L) ? acc[i][j + 2] * scale : NEGV;
            r.w = (qok && (k + 3) < L) ? acc[i][j + 3] * scale : NEGV;
            *(float4*)(outp + (size_t)q * SS + k) = r;
        }
    }
}

// ---------------------------------------------------------------------------
// Kernel 3: row softmax over last axis (rows of length SS).
// grid: BB*SS blocks of 256 threads; 8 elements per thread.
// ---------------------------------------------------------------------------
__global__ __launch_bounds__(256) void softmax_k()
{
    float* row = g_p + (size_t)blockIdx.x * SS;
    int tid = threadIdx.x;

    float x[8];
    *(float4*)&x[0] = *(float4*)(row + tid * 8);
    *(float4*)&x[4] = *(float4*)(row + tid * 8 + 4);

    float m = x[0];
#pragma unroll
    for (int i = 1; i < 8; i++) m = fmaxf(m, x[i]);
#pragma unroll
    for (int o = 16; o > 0; o >>= 1) m = fmaxf(m, __shfl_xor_sync(0xffffffffu, m, o));

    __shared__ float smax[8];
    __shared__ float ssum[8];
    if ((tid & 31) == 0) smax[tid >> 5] = m;
    __syncthreads();
    float bm = smax[0];
#pragma unroll
    for (int i = 1; i < 8; i++) bm = fmaxf(bm, smax[i]);

    float s = 0.f;
#pragma unroll
    for (int i = 0; i < 8; i++) { x[i] = __expf(x[i] - bm); s += x[i]; }
#pragma unroll
    for (int o = 16; o > 0; o >>= 1) s += __shfl_xor_sync(0xffffffffu, s, o);
    if ((tid & 31) == 0) ssum[tid >> 5] = s;
    __syncthreads();
    float ts = 0.f;
#pragma unroll
    for (int i = 0; i < 8; i++) ts += ssum[i];

    float inv = 1.0f / ts;
#pragma unroll
    for (int i = 0; i < 8; i++) x[i] *= inv;
    *(float4*)(row + tid * 8)     = *(float4*)&x[0];
    *(float4*)(row + tid * 8 + 4) = *(float4*)&x[4];
}

// ---------------------------------------------------------------------------
// Kernel 4: out[b,q,d] = sum_k P[b,q,k] * V[b,k,d]   (NN gemm, K=SS)
// grid: (DD/128, SS/128, BB)
// ---------------------------------------------------------------------------
__global__ __launch_bounds__(256) void pv_gemm(float* __restrict__ out)
{
    int b = blockIdx.z;
    int q0 = blockIdx.y * 128;
    int d0 = blockIdx.x * 128;

    __shared__ float As[16][132];
    __shared__ float Bs[16][132];

    int tid = threadIdx.x;
    int ty = tid >> 4, tx = tid & 15;

    int lr = tid >> 2;
    int lc = (tid & 3) * 4;
    int br = tid >> 5;          // 0..7
    int bc = (tid & 31) * 4;    // 0..124

    const float* Aptr = g_p + (size_t)b * SS * SS + (size_t)q0 * SS;
    const float* Vb   = g_v + (size_t)b * SS * DD;

    float acc[8][8] = {};

    for (int k0 = 0; k0 < SS; k0 += 16) {
#pragma unroll
        for (int h = 0; h < 2; h++) {
            int row = lr + h * 64;
            float4 a = *(const float4*)(Aptr + (size_t)row * SS + k0 + lc);
            As[lc + 0][row] = a.x; As[lc + 1][row] = a.y;
            As[lc + 2][row] = a.z; As[lc + 3][row] = a.w;
            int vr = br + h * 8;
            float4 v4 = *(const float4*)(Vb + (size_t)(k0 + vr) * DD + d0 + bc);
            *(float4*)&Bs[vr][bc] = v4;
        }
        __syncthreads();
#pragma unroll
        for (int kk = 0; kk < 16; kk++) {
            float a[8], bb[8];
            *(float4*)&a[0]  = *(const float4*)&As[kk][ty * 8];
            *(float4*)&a[4]  = *(const float4*)&As[kk][ty * 8 + 4];
            *(float4*)&bb[0] = *(const float4*)&Bs[kk][tx * 8];
            *(float4*)&bb[4] = *(const float4*)&Bs[kk][tx * 8 + 4];
#pragma unroll
            for (int i = 0; i < 8; i++)
#pragma unroll
                for (int j = 0; j < 8; j++)
                    acc[i][j] += a[i] * bb[j];
        }
        __syncthreads();
    }

#pragma unroll
    for (int i = 0; i < 8; i++) {
        int q = q0 + ty * 8 + i;
#pragma unroll
        for (int j = 0; j < 8; j += 4) {
            int d = d0 + tx * 8 + j;
            float4 r;
            r.x = acc[i][j + 0];
            r.y = acc[i][j + 1];
            r.z = acc[i][j + 2];
            r.w = acc[i][j + 3];
            *(float4*)(out + (size_t)(b * SS + q) * DD + d) = r;
        }
    }
}

// ---------------------------------------------------------------------------
extern "C" void kernel_launch(void* const* d_in, const int* in_sizes, int n_in,
                              void* d_out, int out_size)
{
    const float* x  = (const float*)d_in[0];
    const int*   ev = (const int*)  d_in[1];
    const float* Wq = (const float*)d_in[2];
    const float* bq = (const float*)d_in[3];
    const float* Wk = (const float*)d_in[4];
    const float* bk = (const float*)d_in[5];
    const float* Wv = (const float*)d_in[6];
    const float* bv = (const float*)d_in[7];
    float* out = (float*)d_out;

    qkv_gemm  <<<dim3(DD / 128, (BB * SS) / 128, 3), 256>>>(x, Wq, bq, Wk, bk, Wv, bv);
    scores_gemm<<<dim3(SS / 128, SS / 128, BB), 256>>>(ev);
    softmax_k <<<BB * SS, 256>>>();
    pv_gemm   <<<dim3(DD / 128, SS / 128, BB), 256>>>(out);
}

// round 4
// speedup vs baseline: 1.6770x; 1.6770x over previous
#include <cuda_runtime.h>
#include <cstdint>

#define BB 8
#define SS 2048
#define DD 512
#define SCALEV 0.04419417382415922f   // 1/sqrt(512)

// ---- GEMM tile config ----
#define BM 128
#define BN 128
#define BK 32
#define STAGES 2
#define RS 36                          // smem row stride (floats), conflict-free
#define AFLOATS (BM*RS)
#define STAGE_FLOATS (2*AFLOATS)
#define SMEM_BYTES (STAGES*STAGE_FLOATS*4)   // 73728

// ---- scratch ----
__device__ float g_q[BB*SS*DD];
__device__ float g_k[BB*SS*DD];
__device__ float g_v[BB*SS*DD];
__device__ float g_vt[BB*SS*DD];
__device__ float g_vmean[BB*DD];
__device__ float g_p[(size_t)BB*SS*SS];

// ============================ helpers ============================
__device__ __forceinline__ uint32_t smem_u32(const void* p) {
    uint32_t a;
    asm("{ .reg .u64 t; cvta.to.shared.u64 t, %1; cvt.u32.u64 %0, t; }" : "=r"(a) : "l"(p));
    return a;
}
__device__ __forceinline__ void cp16(uint32_t dst, const float* src) {
    asm volatile("cp.async.cg.shared.global [%0], [%1], 16;" :: "r"(dst), "l"(src));
}
#define CP_COMMIT() asm volatile("cp.async.commit_group;" ::: "memory")
#define CP_WAIT0()  asm volatile("cp.async.wait_group 0;" ::: "memory")

__device__ __forceinline__ uint32_t f2tf32(float x) {
    uint32_t r;
    asm("cvt.rna.tf32.f32 %0, %1;" : "=r"(r) : "f"(x));
    return r;
}
// 3xTF32 split: x ~= hi + lo, both tf32-representable
__device__ __forceinline__ void tf32_split(float x, uint32_t& hi, uint32_t& lo) {
    hi = f2tf32(x);
    lo = f2tf32(x - __uint_as_float(hi));
}

__device__ __forceinline__ void mma_tf32(float* c, const uint32_t* a, uint32_t b0, uint32_t b1) {
    asm volatile(
        "mma.sync.aligned.m16n8k8.row.col.f32.tf32.tf32.f32 "
        "{%0,%1,%2,%3},{%4,%5,%6,%7},{%8,%9},{%0,%1,%2,%3};"
        : "+f"(c[0]), "+f"(c[1]), "+f"(c[2]), "+f"(c[3])
        : "r"(a[0]), "r"(a[1]), "r"(a[2]), "r"(a[3]), "r"(b0), "r"(b1));
}

// load one BK-chunk (A 128x32, B 128x32) into stage s
__device__ __forceinline__ void load_chunk(
    const float* __restrict__ Ag, size_t lda,
    const float* __restrict__ Bg, size_t ldb,
    int c, int s, uint32_t smaddr, int tid)
{
    const float* Ac = Ag + (size_t)c * BK;
    const float* Bc = Bg + (size_t)c * BK;
    uint32_t base = smaddr + s * (STAGE_FLOATS * 4);
#pragma unroll
    for (int i = 0; i < 4; i++) {
        int idx = tid + i * 256;
        int r = idx >> 3, cg = (idx & 7) * 4;
        cp16(base + (r * RS + cg) * 4, Ac + (size_t)r * lda + cg);
    }
#pragma unroll
    for (int i = 0; i < 4; i++) {
        int idx = tid + i * 256;
        int r = idx >> 3, cg = (idx & 7) * 4;
        cp16(base + (AFLOATS + r * RS + cg) * 4, Bc + (size_t)r * ldb + cg);
    }
}

// D[128,128] += A(128 x K) * B(128 x K)^T, both K-major, via 3xTF32.
__device__ __forceinline__ void mma_mainloop(
    const float* __restrict__ Ag, size_t lda,
    const float* __restrict__ Bg, size_t ldb,
    int nchunks, const float* sm, uint32_t smaddr,
    float acc[2][8][4])
{
    const int tid = threadIdx.x;
    const int lane = tid & 31, wid = tid >> 5;
    const int gid = lane >> 2, tig = lane & 3;
    const int m_base = (wid & 3) * 32;
    const int n_base = (wid >> 2) * 64;

    if (0 < nchunks) load_chunk(Ag, lda, Bg, ldb, 0, 0, smaddr, tid);
    CP_COMMIT();

    for (int c = 0; c < nchunks; c++) {
        CP_WAIT0();
        __syncthreads();
        if (c + 1 < nchunks)
            load_chunk(Ag, lda, Bg, ldb, c + 1, (c + 1) & 1, smaddr, tid);
        CP_COMMIT();

        const float* as = sm + (c & 1) * STAGE_FLOATS;
        const float* ab = as + (m_base + gid) * RS + tig;
        const float* bb = as + AFLOATS + (n_base + gid) * RS + tig;
#pragma unroll
        for (int ks = 0; ks < 4; ks++) {
            uint32_t ah[2][4], al[2][4];
#pragma unroll
            for (int mf = 0; mf < 2; mf++) {
                tf32_split(ab[(mf*16    ) * RS + ks*8    ], ah[mf][0], al[mf][0]);
                tf32_split(ab[(mf*16 + 8) * RS + ks*8    ], ah[mf][1], al[mf][1]);
                tf32_split(ab[(mf*16    ) * RS + ks*8 + 4], ah[mf][2], al[mf][2]);
                tf32_split(ab[(mf*16 + 8) * RS + ks*8 + 4], ah[mf][3], al[mf][3]);
            }
#pragma unroll
            for (int nf = 0; nf < 8; nf++) {
                uint32_t bh0, bl0, bh1, bl1;
                tf32_split(bb[(nf*8) * RS + ks*8    ], bh0, bl0);
                tf32_split(bb[(nf*8) * RS + ks*8 + 4], bh1, bl1);
                // correction terms first, hi*hi last
                mma_tf32(acc[0][nf], al[0], bh0, bh1);
                mma_tf32(acc[1][nf], al[1], bh0, bh1);
                mma_tf32(acc[0][nf], ah[0], bl0, bl1);
                mma_tf32(acc[1][nf], ah[1], bl0, bl1);
                mma_tf32(acc[0][nf], ah[0], bh0, bh1);
                mma_tf32(acc[1][nf], ah[1], bh0, bh1);
            }
        }
    }
}

// ============================ kernel 1: QKV ============================
__global__ __launch_bounds__(256, 2) void qkv_k(
    const float* __restrict__ x,
    const float* __restrict__ Wq, const float* __restrict__ bq,
    const float* __restrict__ Wk, const float* __restrict__ bk,
    const float* __restrict__ Wv, const float* __restrict__ bv)
{
    extern __shared__ float dsm[];
    uint32_t smaddr = smem_u32(dsm);

    int m0 = blockIdx.x * BM;
    int e0 = blockIdx.y * BN;
    const float* W; const float* bias; float* out;
    if (blockIdx.z == 0)      { W = Wq; bias = bq; out = g_q; }
    else if (blockIdx.z == 1) { W = Wk; bias = bk; out = g_k; }
    else                      { W = Wv; bias = bv; out = g_v; }

    float acc[2][8][4] = {};
    mma_mainloop(x + (size_t)m0 * DD, DD, W + (size_t)e0 * DD, DD,
                 DD / BK, dsm, smaddr, acc);

    int tid = threadIdx.x, lane = tid & 31, wid = tid >> 5;
    int gid = lane >> 2, tig = lane & 3;
    int row0 = m0 + (wid & 3) * 32 + gid;
    int col0 = e0 + (wid >> 2) * 64 + tig * 2;
#pragma unroll
    for (int mf = 0; mf < 2; mf++)
#pragma unroll
    for (int h = 0; h < 2; h++) {
        int row = row0 + mf * 16 + h * 8;
#pragma unroll
        for (int nf = 0; nf < 8; nf++) {
            int col = col0 + nf * 8;
            float2 v;
            v.x = acc[mf][nf][h*2+0] + bias[col];
            v.y = acc[mf][nf][h*2+1] + bias[col+1];
            *(float2*)(out + (size_t)row * DD + col) = v;
        }
    }
}

// ============================ kernel 2: scores ============================
__global__ __launch_bounds__(256, 2) void scores_k(const int* __restrict__ ev)
{
    int b = blockIdx.z;
    int L = ev[b];
    int q0 = blockIdx.x * BM;
    int k0 = blockIdx.y * BN;
    if (q0 >= L || k0 >= L) return;    // never read downstream

    extern __shared__ float dsm[];
    uint32_t smaddr = smem_u32(dsm);

    float acc[2][8][4] = {};
    mma_mainloop(g_q + ((size_t)b * SS + q0) * DD, DD,
                 g_k + ((size_t)b * SS + k0) * DD, DD,
                 DD / BK, dsm, smaddr, acc);

    float* P = g_p + (size_t)b * SS * SS;
    int tid = threadIdx.x, lane = tid & 31, wid = tid >> 5;
    int gid = lane >> 2, tig = lane & 3;
    int row0 = q0 + (wid & 3) * 32 + gid;
    int col0 = k0 + (wid >> 2) * 64 + tig * 2;
#pragma unroll
    for (int mf = 0; mf < 2; mf++)
#pragma unroll
    for (int h = 0; h < 2; h++) {
        int q = row0 + mf * 16 + h * 8;
        if (q >= L) continue;
#pragma unroll
        for (int nf = 0; nf < 8; nf++) {
            int k = col0 + nf * 8;
            if (k + 1 < L) {
                float2 v;
                v.x = acc[mf][nf][h*2+0] * SCALEV;
                v.y = acc[mf][nf][h*2+1] * SCALEV;
                *(float2*)(P + (size_t)q * SS + k) = v;
            } else if (k < L) {
                P[(size_t)q * SS + k] = acc[mf][nf][h*2+0] * SCALEV;
            }
        }
    }
}

// ============================ kernel 3: softmax ============================
__global__ __launch_bounds__(256) void softmax_k(const int* __restrict__ ev)
{
    int b = blockIdx.y;
    int q = blockIdx.x;
    int L = ev[b];
    if (q >= L) return;                 // handled via vmean in pv
    float* row = g_p + ((size_t)b * SS + q) * SS;
    int tid = threadIdx.x;

    float vals[8];
    float m = -3.4e38f;
#pragma unroll
    for (int i = 0; i < 8; i++) {
        int k = tid + i * 256;
        vals[i] = (k < L) ? row[k] : -3.4e38f;
        m = fmaxf(m, vals[i]);
    }
#pragma unroll
    for (int o = 16; o > 0; o >>= 1) m = fmaxf(m, __shfl_xor_sync(0xffffffffu, m, o));
    __shared__ float sred[8];
    if ((tid & 31) == 0) sred[tid >> 5] = m;
    __syncthreads();
    float bm = sred[0];
#pragma unroll
    for (int i = 1; i < 8; i++) bm = fmaxf(bm, sred[i]);
    __syncthreads();

    float s = 0.f;
#pragma unroll
    for (int i = 0; i < 8; i++) {
        int k = tid + i * 256;
        vals[i] = (k < L) ? __expf(vals[i] - bm) : 0.f;
        s += vals[i];
    }
#pragma unroll
    for (int o = 16; o > 0; o >>= 1) s += __shfl_xor_sync(0xffffffffu, s, o);
    if ((tid & 31) == 0) sred[tid >> 5] = s;
    __syncthreads();
    float ts = 0.f;
#pragma unroll
    for (int i = 0; i < 8; i++) ts += sred[i];
    float inv = 1.0f / ts;

#pragma unroll
    for (int i = 0; i < 8; i++) {
        int k = tid + i * 256;
        if (k < L) row[k] = vals[i] * inv;
    }
    int pad = (L + 31) & ~31;            // zero-fill to BK boundary for pv
    if (pad > SS) pad = SS;
    for (int k = L + tid; k < pad; k += 256) row[k] = 0.f;
}

// ============================ transpose V -> vT ============================
__global__ void vtrans_k()
{
    __shared__ float t[32][33];
    int b = blockIdx.z;
    int s0 = blockIdx.x * 32;
    int d0 = blockIdx.y * 32;
    int tx = threadIdx.x, ty = threadIdx.y;
    const float* v = g_v + (size_t)b * SS * DD;
    float* vt = g_vt + (size_t)b * DD * SS;
#pragma unroll
    for (int i = 0; i < 4; i++)
        t[ty + i*8][tx] = v[(size_t)(s0 + ty + i*8) * DD + d0 + tx];
    __syncthreads();
#pragma unroll
    for (int i = 0; i < 4; i++)
        vt[(size_t)(d0 + ty + i*8) * SS + s0 + tx] = t[tx][ty + i*8];
}

// ============================ vmean (deterministic) ============================
__global__ __launch_bounds__(256) void vmean_k()
{
    int b = blockIdx.x;
    int d = blockIdx.y * 256 + threadIdx.x;
    const float* v = g_v + (size_t)b * SS * DD + d;
    float s0 = 0.f, s1 = 0.f, s2 = 0.f, s3 = 0.f;
    for (int s = 0; s < SS; s += 4) {
        s0 += v[(size_t)(s+0) * DD];
        s1 += v[(size_t)(s+1) * DD];
        s2 += v[(size_t)(s+2) * DD];
        s3 += v[(size_t)(s+3) * DD];
    }
    g_vmean[b * DD + d] = (s0 + s1 + s2 + s3) * (1.0f / SS);
}

// ============================ kernel 4: P @ V ============================
__global__ __launch_bounds__(256, 2) void pv_k(const int* __restrict__ ev, float* __restrict__ out)
{
    int b = blockIdx.z;
    int L = ev[b];
    int q0 = blockIdx.x * BM;
    int d0 = blockIdx.y * BN;

    if (q0 >= L) {   // uniform attention -> vmean broadcast
        const float* vm = g_vmean + b * DD + d0;
        for (int idx = threadIdx.x; idx < BM * (BN / 4); idx += 256) {
            int r = idx >> 5, c4 = (idx & 31) * 4;
            float4 v = *(const float4*)(vm + c4);
            *(float4*)(out + ((size_t)(b * SS + q0 + r)) * DD + d0 + c4) = v;
        }
        return;
    }

    extern __shared__ float dsm[];
    uint32_t smaddr = smem_u32(dsm);

    int pad = (L + 31) & ~31;
    if (pad > SS) pad = SS;
    int nchunks = pad / BK;

    float acc[2][8][4] = {};
    mma_mainloop(g_p  + ((size_t)b * SS + q0) * SS, SS,
                 g_vt + ((size_t)b * DD + d0) * SS, SS,
                 nchunks, dsm, smaddr, acc);

    int tid = threadIdx.x, lane = tid & 31, wid = tid >> 5;
    int gid = lane >> 2, tig = lane & 3;
    int row0 = q0 + (wid & 3) * 32 + gid;
    int col0 = d0 + (wid >> 2) * 64 + tig * 2;
    const float* vm = g_vmean + b * DD;
#pragma unroll
    for (int mf = 0; mf < 2; mf++)
#pragma unroll
    for (int h = 0; h < 2; h++) {
        int q = row0 + mf * 16 + h * 8;
        bool qok = q < L;
#pragma unroll
        for (int nf = 0; nf < 8; nf++) {
            int col = col0 + nf * 8;
            float2 v;
            if (qok) { v.x = acc[mf][nf][h*2+0]; v.y = acc[mf][nf][h*2+1]; }
            else     { v.x = vm[col];            v.y = vm[col+1]; }
            *(float2*)(out + (size_t)(b * SS + q) * DD + col) = v;
        }
    }
}

// ============================ launch ============================
extern "C" void kernel_launch(void* const* d_in, const int* in_sizes, int n_in,
                              void* d_out, int out_size)
{
    const float* x  = (const float*)d_in[0];
    const int*   ev = (const int*)  d_in[1];
    const float* Wq = (const float*)d_in[2];
    const float* bq = (const float*)d_in[3];
    const float* Wk = (const float*)d_in[4];
    const float* bk = (const float*)d_in[5];
    const float* Wv = (const float*)d_in[6];
    const float* bv = (const float*)d_in[7];
    float* out = (float*)d_out;

    cudaFuncSetAttribute(qkv_k,    cudaFuncAttributeMaxDynamicSharedMemorySize, SMEM_BYTES);
    cudaFuncSetAttribute(scores_k, cudaFuncAttributeMaxDynamicSharedMemorySize, SMEM_BYTES);
    cudaFuncSetAttribute(pv_k,     cudaFuncAttributeMaxDynamicSharedMemorySize, SMEM_BYTES);

    qkv_k   <<<dim3((BB*SS)/BM, DD/BN, 3), 256, SMEM_BYTES>>>(x, Wq, bq, Wk, bk, Wv, bv);
    vtrans_k<<<dim3(SS/32, DD/32, BB), dim3(32, 8)>>>();
    vmean_k <<<dim3(BB, DD/256), 256>>>();
    scores_k<<<dim3(SS/BM, SS/BN, BB), 256, SMEM_BYTES>>>(ev);
    softmax_k<<<dim3(SS, BB), 256>>>(ev);
    pv_k    <<<dim3(SS/BM, DD/BN, BB), 256, SMEM_BYTES>>>(ev, out);
}

// round 5
// speedup vs baseline: 2.7931x; 1.6655x over previous
#include <cuda_runtime.h>
#include <cuda_bf16.h>
#include <cstdint>

#define BB 8
#define SS 2048
#define DD 512
#define SCALEV 0.04419417382415922f   // 1/sqrt(512)

// ---- GEMM tile config ----
#define BM 128
#define BN 128
#define BK 32
#define RS32 20                        // u32 row stride (32 bf16 = 16 u32 data + pad) -> conflict-free
#define TILE_U32 (128*RS32)            // 2560
#define STAGE_U32 (4*TILE_U32)         // Ah, Al, Bh, Bl
#define SMEM_BYTES (2*STAGE_U32*4)     // 81920

// ---- scratch (bf16 hi/lo pairs) ----
__device__ __nv_bfloat16 g_xh[BB*SS*DD], g_xl[BB*SS*DD];
__device__ __nv_bfloat16 g_wh[3*DD*DD], g_wl[3*DD*DD];
__device__ __nv_bfloat16 g_qh[BB*SS*DD], g_ql[BB*SS*DD];
__device__ __nv_bfloat16 g_kh[BB*SS*DD], g_kl[BB*SS*DD];
__device__ float g_v[BB*SS*DD];
__device__ __nv_bfloat16 g_vth[BB*DD*SS], g_vtl[BB*DD*SS];
__device__ float g_vmean[BB*DD];
__device__ float g_p[(size_t)BB*SS*SS];
__device__ __nv_bfloat16 g_ph[(size_t)BB*SS*SS], g_pl[(size_t)BB*SS*SS];

// ============================ helpers ============================
__device__ __forceinline__ uint32_t smem_u32(const void* p) {
    uint32_t a;
    asm("{ .reg .u64 t; cvta.to.shared.u64 t, %1; cvt.u32.u64 %0, t; }" : "=r"(a) : "l"(p));
    return a;
}
__device__ __forceinline__ void cp16(uint32_t dst, const void* src) {
    asm volatile("cp.async.cg.shared.global [%0], [%1], 16;" :: "r"(dst), "l"(src));
}
#define CP_COMMIT() asm volatile("cp.async.commit_group;" ::: "memory")
#define CP_WAIT0()  asm volatile("cp.async.wait_group 0;" ::: "memory")

__device__ __forceinline__ void bf16split(float x, __nv_bfloat16& h, __nv_bfloat16& l) {
    h = __float2bfloat16(x);
    l = __float2bfloat16(x - __bfloat162float(h));
}

__device__ __forceinline__ void mma_bf16(float* c, const uint32_t* a, uint32_t b0, uint32_t b1) {
    asm volatile(
        "mma.sync.aligned.m16n8k16.row.col.f32.bf16.bf16.f32 "
        "{%0,%1,%2,%3},{%4,%5,%6,%7},{%8,%9},{%0,%1,%2,%3};"
        : "+f"(c[0]), "+f"(c[1]), "+f"(c[2]), "+f"(c[3])
        : "r"(a[0]), "r"(a[1]), "r"(a[2]), "r"(a[3]), "r"(b0), "r"(b1));
}

// load one BK-chunk of all 4 tiles (Ah/Al 128x32, Bh/Bl 128x32 bf16) into stage s
__device__ __forceinline__ void load_chunk(
    const __nv_bfloat16* __restrict__ Ah, const __nv_bfloat16* __restrict__ Al, size_t lda,
    const __nv_bfloat16* __restrict__ Bh, const __nv_bfloat16* __restrict__ Bl, size_t ldb,
    int c, int s, uint32_t smaddr, int tid)
{
    uint32_t base = smaddr + s * (STAGE_U32 * 4);
    const __nv_bfloat16* ah = Ah + (size_t)c * BK;
    const __nv_bfloat16* al = Al + (size_t)c * BK;
    const __nv_bfloat16* bh = Bh + (size_t)c * BK;
    const __nv_bfloat16* bl = Bl + (size_t)c * BK;
#pragma unroll
    for (int i = 0; i < 2; i++) {
        int idx = tid + i * 256;
        int r = idx >> 2, cg = (idx & 3) * 4;       // cg: u32 offset in row
        uint32_t doff = (uint32_t)(r * RS32 + cg) * 4;
        cp16(base + doff,                  ah + (size_t)r * lda + cg * 2);
        cp16(base + TILE_U32*4   + doff,   al + (size_t)r * lda + cg * 2);
        cp16(base + 2*TILE_U32*4 + doff,   bh + (size_t)r * ldb + cg * 2);
        cp16(base + 3*TILE_U32*4 + doff,   bl + (size_t)r * ldb + cg * 2);
    }
}

// D[128,128] += A(128 x K) * B(128 x K)^T, K-major bf16 hi/lo, 3-term split.
__device__ __forceinline__ void mma_mainloop(
    const __nv_bfloat16* __restrict__ Ah, const __nv_bfloat16* __restrict__ Al, size_t lda,
    const __nv_bfloat16* __restrict__ Bh, const __nv_bfloat16* __restrict__ Bl, size_t ldb,
    int nchunks, const uint32_t* sm, uint32_t smaddr,
    float acc[2][8][4])
{
    const int tid = threadIdx.x;
    const int lane = tid & 31, wid = tid >> 5;
    const int gid = lane >> 2, tig = lane & 3;
    const int m_base = (wid & 3) * 32;
    const int n_base = (wid >> 2) * 64;

    if (0 < nchunks) load_chunk(Ah, Al, lda, Bh, Bl, ldb, 0, 0, smaddr, tid);
    CP_COMMIT();

    for (int c = 0; c < nchunks; c++) {
        CP_WAIT0();
        __syncthreads();
        if (c + 1 < nchunks)
            load_chunk(Ah, Al, lda, Bh, Bl, ldb, c + 1, (c + 1) & 1, smaddr, tid);
        CP_COMMIT();

        const uint32_t* st = sm + (c & 1) * STAGE_U32;
        const uint32_t* ahb = st + (m_base + gid) * RS32 + tig;
        const uint32_t* alb = ahb + TILE_U32;
        const uint32_t* bhb = st + 2*TILE_U32 + (n_base + gid) * RS32 + tig;
        const uint32_t* blb = bhb + TILE_U32;
#pragma unroll
        for (int ks = 0; ks < 2; ks++) {
            int ko = ks * 8;
            uint32_t ah[2][4], al[2][4];
#pragma unroll
            for (int mf = 0; mf < 2; mf++) {
                ah[mf][0] = ahb[(mf*16    ) * RS32 + ko    ];
                ah[mf][1] = ahb[(mf*16 + 8) * RS32 + ko    ];
                ah[mf][2] = ahb[(mf*16    ) * RS32 + ko + 4];
                ah[mf][3] = ahb[(mf*16 + 8) * RS32 + ko + 4];
                al[mf][0] = alb[(mf*16    ) * RS32 + ko    ];
                al[mf][1] = alb[(mf*16 + 8) * RS32 + ko    ];
                al[mf][2] = alb[(mf*16    ) * RS32 + ko + 4];
                al[mf][3] = alb[(mf*16 + 8) * RS32 + ko + 4];
            }
#pragma unroll
            for (int nf = 0; nf < 8; nf++) {
                uint32_t bh0 = bhb[(nf*8) * RS32 + ko];
                uint32_t bh1 = bhb[(nf*8) * RS32 + ko + 4];
                uint32_t bl0 = blb[(nf*8) * RS32 + ko];
                uint32_t bl1 = blb[(nf*8) * RS32 + ko + 4];
                mma_bf16(acc[0][nf], al[0], bh0, bh1);
                mma_bf16(acc[1][nf], al[1], bh0, bh1);
                mma_bf16(acc[0][nf], ah[0], bl0, bl1);
                mma_bf16(acc[1][nf], ah[1], bl0, bl1);
                mma_bf16(acc[0][nf], ah[0], bh0, bh1);
                mma_bf16(acc[1][nf], ah[1], bh0, bh1);
            }
        }
    }
}

// ============================ split inputs ============================
// which: 0 -> x, 1..3 -> Wq/Wk/Wv
__global__ __launch_bounds__(256) void split_k(const float4* __restrict__ in, int which, int n4)
{
    int i = blockIdx.x * 256 + threadIdx.x;
    if (i >= n4) return;
    __nv_bfloat162* h2; __nv_bfloat162* l2;
    if (which == 0) { h2 = (__nv_bfloat162*)g_xh; l2 = (__nv_bfloat162*)g_xl; }
    else {
        h2 = (__nv_bfloat162*)(g_wh + (size_t)(which - 1) * DD * DD);
        l2 = (__nv_bfloat162*)(g_wl + (size_t)(which - 1) * DD * DD);
    }
    float4 v = in[i];
    __nv_bfloat16 h0, l0, h1, l1;
    bf16split(v.x, h0, l0); bf16split(v.y, h1, l1);
    h2[i*2]   = __nv_bfloat162(h0, h1);
    l2[i*2]   = __nv_bfloat162(l0, l1);
    bf16split(v.z, h0, l0); bf16split(v.w, h1, l1);
    h2[i*2+1] = __nv_bfloat162(h0, h1);
    l2[i*2+1] = __nv_bfloat162(l0, l1);
}

// ============================ kernel 1: QKV ============================
__global__ __launch_bounds__(256, 2) void qkv_k(
    const float* __restrict__ bq, const float* __restrict__ bk, const float* __restrict__ bv)
{
    extern __shared__ uint32_t dsm[];
    uint32_t smaddr = smem_u32(dsm);

    int m0 = blockIdx.x * BM;
    int e0 = blockIdx.y * BN;
    int z = blockIdx.z;
    const float* bias = (z == 0) ? bq : (z == 1) ? bk : bv;

    float acc[2][8][4] = {};
    mma_mainloop(g_xh + (size_t)m0 * DD, g_xl + (size_t)m0 * DD, DD,
                 g_wh + (size_t)z * DD * DD + (size_t)e0 * DD,
                 g_wl + (size_t)z * DD * DD + (size_t)e0 * DD, DD,
                 DD / BK, dsm, smaddr, acc);

    int tid = threadIdx.x, lane = tid & 31, wid = tid >> 5;
    int gid = lane >> 2, tig = lane & 3;
    int row0 = m0 + (wid & 3) * 32 + gid;
    int col0 = e0 + (wid >> 2) * 64 + tig * 2;
#pragma unroll
    for (int mf = 0; mf < 2; mf++)
#pragma unroll
    for (int h = 0; h < 2; h++) {
        int row = row0 + mf * 16 + h * 8;
#pragma unroll
        for (int nf = 0; nf < 8; nf++) {
            int col = col0 + nf * 8;
            float y0 = acc[mf][nf][h*2+0] + bias[col];
            float y1 = acc[mf][nf][h*2+1] + bias[col+1];
            size_t off = (size_t)row * DD + col;
            if (z == 2) {
                *(float2*)(g_v + off) = make_float2(y0, y1);
            } else {
                __nv_bfloat16 h0, l0, h1, l1;
                bf16split(y0, h0, l0); bf16split(y1, h1, l1);
                __nv_bfloat16* oh = (z == 0) ? g_qh : g_kh;
                __nv_bfloat16* ol = (z == 0) ? g_ql : g_kl;
                *(__nv_bfloat162*)(oh + off) = __nv_bfloat162(h0, h1);
                *(__nv_bfloat162*)(ol + off) = __nv_bfloat162(l0, l1);
            }
        }
    }
}

// ============================ kernel 2: scores ============================
__global__ __launch_bounds__(256, 2) void scores_k(const int* __restrict__ ev)
{
    int b = blockIdx.z;
    int L = ev[b];
    int q0 = blockIdx.x * BM;
    int k0 = blockIdx.y * BN;
    if (q0 >= L || k0 >= L) return;    // never read downstream

    extern __shared__ uint32_t dsm[];
    uint32_t smaddr = smem_u32(dsm);

    float acc[2][8][4] = {};
    size_t qoff = ((size_t)b * SS + q0) * DD;
    size_t koff = ((size_t)b * SS + k0) * DD;
    mma_mainloop(g_qh + qoff, g_ql + qoff, DD,
                 g_kh + koff, g_kl + koff, DD,
                 DD / BK, dsm, smaddr, acc);

    float* P = g_p + (size_t)b * SS * SS;
    int tid = threadIdx.x, lane = tid & 31, wid = tid >> 5;
    int gid = lane >> 2, tig = lane & 3;
    int row0 = q0 + (wid & 3) * 32 + gid;
    int col0 = k0 + (wid >> 2) * 64 + tig * 2;
#pragma unroll
    for (int mf = 0; mf < 2; mf++)
#pragma unroll
    for (int h = 0; h < 2; h++) {
        int q = row0 + mf * 16 + h * 8;
        if (q >= L) continue;
#pragma unroll
        for (int nf = 0; nf < 8; nf++) {
            int k = col0 + nf * 8;
            if (k + 1 < L) {
                float2 v;
                v.x = acc[mf][nf][h*2+0] * SCALEV;
                v.y = acc[mf][nf][h*2+1] * SCALEV;
                *(float2*)(P + (size_t)q * SS + k) = v;
            } else if (k < L) {
                P[(size_t)q * SS + k] = acc[mf][nf][h*2+0] * SCALEV;
            }
        }
    }
}

// ============================ kernel 3: softmax ============================
__global__ __launch_bounds__(256) void softmax_k(const int* __restrict__ ev)
{
    int b = blockIdx.y;
    int q = blockIdx.x;
    int L = ev[b];
    if (q >= L) return;                 // handled via vmean in pv
    size_t off = ((size_t)b * SS + q) * SS;
    const float* row = g_p + off;
    int tid = threadIdx.x;

    float vals[8];
    float m = -3.4e38f;
#pragma unroll
    for (int i = 0; i < 8; i++) {
        int k = tid + i * 256;
        vals[i] = (k < L) ? row[k] : -3.4e38f;
        m = fmaxf(m, vals[i]);
    }
#pragma unroll
    for (int o = 16; o > 0; o >>= 1) m = fmaxf(m, __shfl_xor_sync(0xffffffffu, m, o));
    __shared__ float sred[8];
    if ((tid & 31) == 0) sred[tid >> 5] = m;
    __syncthreads();
    float bm = sred[0];
#pragma unroll
    for (int i = 1; i < 8; i++) bm = fmaxf(bm, sred[i]);
    __syncthreads();

    float s = 0.f;
#pragma unroll
    for (int i = 0; i < 8; i++) {
        int k = tid + i * 256;
        vals[i] = (k < L) ? __expf(vals[i] - bm) : 0.f;
        s += vals[i];
    }
#pragma unroll
    for (int o = 16; o > 0; o >>= 1) s += __shfl_xor_sync(0xffffffffu, s, o);
    if ((tid & 31) == 0) sred[tid >> 5] = s;
    __syncthreads();
    float ts = 0.f;
#pragma unroll
    for (int i = 0; i < 8; i++) ts += sred[i];
    float inv = 1.0f / ts;

#pragma unroll
    for (int i = 0; i < 8; i++) {
        int k = tid + i * 256;
        if (k < L) {
            float p = vals[i] * inv;
            __nv_bfloat16 h, l;
            bf16split(p, h, l);
            g_ph[off + k] = h;
            g_pl[off + k] = l;
        }
    }
    int pad = (L + 31) & ~31;            // zero-fill to BK boundary for pv
    if (pad > SS) pad = SS;
    __nv_bfloat16 z = __float2bfloat16(0.f);
    for (int k = L + tid; k < pad; k += 256) { g_ph[off + k] = z; g_pl[off + k] = z; }
}

// ============================ transpose V -> vT (split) ============================
__global__ void vtrans_k()
{
    __shared__ float t[32][33];
    int b = blockIdx.z;
    int s0 = blockIdx.x * 32;
    int d0 = blockIdx.y * 32;
    int tx = threadIdx.x, ty = threadIdx.y;
    const float* v = g_v + (size_t)b * SS * DD;
#pragma unroll
    for (int i = 0; i < 4; i++)
        t[ty + i*8][tx] = v[(size_t)(s0 + ty + i*8) * DD + d0 + tx];
    __syncthreads();
#pragma unroll
    for (int i = 0; i < 4; i++) {
        float val = t[tx][ty + i*8];
        __nv_bfloat16 h, l;
        bf16split(val, h, l);
        size_t o = (size_t)b * DD * SS + (size_t)(d0 + ty + i*8) * SS + s0 + tx;
        g_vth[o] = h;
        g_vtl[o] = l;
    }
}

// ============================ vmean (deterministic) ============================
__global__ __launch_bounds__(256) void vmean_k()
{
    int b = blockIdx.x;
    int d = blockIdx.y * 256 + threadIdx.x;
    const float* v = g_v + (size_t)b * SS * DD + d;
    float s0 = 0.f, s1 = 0.f, s2 = 0.f, s3 = 0.f;
    for (int s = 0; s < SS; s += 4) {
        s0 += v[(size_t)(s+0) * DD];
        s1 += v[(size_t)(s+1) * DD];
        s2 += v[(size_t)(s+2) * DD];
        s3 += v[(size_t)(s+3) * DD];
    }
    g_vmean[b * DD + d] = (s0 + s1 + s2 + s3) * (1.0f / SS);
}

// ============================ kernel 4: P @ V ============================
__global__ __launch_bounds__(256, 2) void pv_k(const int* __restrict__ ev, float* __restrict__ out)
{
    int b = blockIdx.z;
    int L = ev[b];
    int q0 = blockIdx.x * BM;
    int d0 = blockIdx.y * BN;

    if (q0 >= L) {   // uniform attention -> vmean broadcast
        const float* vm = g_vmean + b * DD + d0;
        for (int idx = threadIdx.x; idx < BM * (BN / 4); idx += 256) {
            int r = idx >> 5, c4 = (idx & 31) * 4;
            float4 v = *(const float4*)(vm + c4);
            *(float4*)(out + ((size_t)(b * SS + q0 + r)) * DD + d0 + c4) = v;
        }
        return;
    }

    extern __shared__ uint32_t dsm[];
    uint32_t smaddr = smem_u32(dsm);

    int pad = (L + 31) & ~31;
    if (pad > SS) pad = SS;
    int nchunks = pad / BK;

    float acc[2][8][4] = {};
    size_t poff = ((size_t)b * SS + q0) * SS;
    size_t voff = ((size_t)b * DD + d0) * SS;
    mma_mainloop(g_ph + poff, g_pl + poff, SS,
                 g_vth + voff, g_vtl + voff, SS,
                 nchunks, dsm, smaddr, acc);

    int tid = threadIdx.x, lane = tid & 31, wid = tid >> 5;
    int gid = lane >> 2, tig = lane & 3;
    int row0 = q0 + (wid & 3) * 32 + gid;
    int col0 = d0 + (wid >> 2) * 64 + tig * 2;
    const float* vm = g_vmean + b * DD;
#pragma unroll
    for (int mf = 0; mf < 2; mf++)
#pragma unroll
    for (int h = 0; h < 2; h++) {
        int q = row0 + mf * 16 + h * 8;
        bool qok = q < L;
#pragma unroll
        for (int nf = 0; nf < 8; nf++) {
            int col = col0 + nf * 8;
            float2 v;
            if (qok) { v.x = acc[mf][nf][h*2+0]; v.y = acc[mf][nf][h*2+1]; }
            else     { v.x = vm[col];            v.y = vm[col+1]; }
            *(float2*)(out + (size_t)(b * SS + q) * DD + col) = v;
        }
    }
}

// ============================ launch ============================
extern "C" void kernel_launch(void* const* d_in, const int* in_sizes, int n_in,
                              void* d_out, int out_size)
{
    const float* x  = (const float*)d_in[0];
    const int*   ev = (const int*)  d_in[1];
    const float* Wq = (const float*)d_in[2];
    const float* bq = (const float*)d_in[3];
    const float* Wk = (const float*)d_in[4];
    const float* bk = (const float*)d_in[5];
    const float* Wv = (const float*)d_in[6];
    const float* bv = (const float*)d_in[7];
    float* out = (float*)d_out;

    cudaFuncSetAttribute(qkv_k,    cudaFuncAttributeMaxDynamicSharedMemorySize, SMEM_BYTES);
    cudaFuncSetAttribute(scores_k, cudaFuncAttributeMaxDynamicSharedMemorySize, SMEM_BYTES);
    cudaFuncSetAttribute(pv_k,     cudaFuncAttributeMaxDynamicSharedMemorySize, SMEM_BYTES);

    int nx4 = BB*SS*DD/4, nw4 = DD*DD/4;
    split_k<<<(nx4 + 255)/256, 256>>>((const float4*)x,  0, nx4);
    split_k<<<(nw4 + 255)/256, 256>>>((const float4*)Wq, 1, nw4);
    split_k<<<(nw4 + 255)/256, 256>>>((const float4*)Wk, 2, nw4);
    split_k<<<(nw4 + 255)/256, 256>>>((const float4*)Wv, 3, nw4);

    qkv_k   <<<dim3((BB*SS)/BM, DD/BN, 3), 256, SMEM_BYTES>>>(bq, bk, bv);
    vtrans_k<<<dim3(SS/32, DD/32, BB), dim3(32, 8)>>>();
    vmean_k <<<dim3(BB, DD/256), 256>>>();
    scores_k<<<dim3(SS/BM, SS/BN, BB), 256, SMEM_BYTES>>>(ev);
    softmax_k<<<dim3(SS, BB), 256>>>(ev);
    pv_k    <<<dim3(SS/BM, DD/BN, BB), 256, SMEM_BYTES>>>(ev, out);
}

// round 6
// speedup vs baseline: 3.0611x; 1.0960x over previous
#include <cuda_runtime.h>
#include <cuda_bf16.h>
#include <cstdint>

#define BB 8
#define SS 2048
#define DD 512
#define SCALEV 0.04419417382415922f   // 1/sqrt(512)

// ---- GEMM tile config ----
#define BM 128
#define BN 128
#define BK 32
#define RS32 20                        // u32 row stride (16 u32 data + 4 pad) -> conflict-free
#define RPB 80                         // row pitch bytes
#define TILE_U32 (128*RS32)            // 2560
#define TBYTES (TILE_U32*4)            // 10240
#define STAGE_U32 (4*TILE_U32)         // Ah, Al, Bh, Bl
#define STAGE_BYTES (STAGE_U32*4)      // 40960
#define SMEM_BYTES (2*STAGE_BYTES)     // 81920

// ---- scratch (bf16 hi/lo pairs) ----
__device__ __nv_bfloat16 g_xh[BB*SS*DD], g_xl[BB*SS*DD];
__device__ __nv_bfloat16 g_wh[3*DD*DD], g_wl[3*DD*DD];
__device__ __nv_bfloat16 g_qh[BB*SS*DD], g_ql[BB*SS*DD];
__device__ __nv_bfloat16 g_kh[BB*SS*DD], g_kl[BB*SS*DD];
__device__ float g_v[BB*SS*DD];
__device__ __nv_bfloat16 g_vth[BB*DD*SS], g_vtl[BB*DD*SS];
__device__ float g_vmean[BB*DD];
__device__ float g_p[(size_t)BB*SS*SS];
__device__ __nv_bfloat16 g_ph[(size_t)BB*SS*SS], g_pl[(size_t)BB*SS*SS];

// ============================ helpers ============================
__device__ __forceinline__ uint32_t smem_u32(const void* p) {
    uint32_t a;
    asm("{ .reg .u64 t; cvta.to.shared.u64 t, %1; cvt.u32.u64 %0, t; }" : "=r"(a) : "l"(p));
    return a;
}
__device__ __forceinline__ void cp16(uint32_t dst, const void* src) {
    asm volatile("cp.async.cg.shared.global [%0], [%1], 16;" :: "r"(dst), "l"(src));
}
#define CP_COMMIT() asm volatile("cp.async.commit_group;" ::: "memory")
#define CP_WAIT0()  asm volatile("cp.async.wait_group 0;" ::: "memory")

__device__ __forceinline__ void bf16split(float x, __nv_bfloat16& h, __nv_bfloat16& l) {
    h = __float2bfloat16(x);
    l = __float2bfloat16(x - __bfloat162float(h));
}

__device__ __forceinline__ void mma_bf16(float* c, const uint32_t* a, uint32_t b0, uint32_t b1) {
    asm volatile(
        "mma.sync.aligned.m16n8k16.row.col.f32.bf16.bf16.f32 "
        "{%0,%1,%2,%3},{%4,%5,%6,%7},{%8,%9},{%0,%1,%2,%3};"
        : "+f"(c[0]), "+f"(c[1]), "+f"(c[2]), "+f"(c[3])
        : "r"(a[0]), "r"(a[1]), "r"(a[2]), "r"(a[3]), "r"(b0), "r"(b1));
}

__device__ __forceinline__ void ldm_x4(uint32_t* r, uint32_t addr) {
    asm volatile("ldmatrix.sync.aligned.m8n8.x4.shared.b16 {%0,%1,%2,%3}, [%4];"
        : "=r"(r[0]), "=r"(r[1]), "=r"(r[2]), "=r"(r[3]) : "r"(addr));
}

// load one BK-chunk of all 4 tiles (Ah/Al 128x32, Bh/Bl 128x32 bf16) into stage s
__device__ __forceinline__ void load_chunk(
    const __nv_bfloat16* __restrict__ Ah, const __nv_bfloat16* __restrict__ Al, size_t lda,
    const __nv_bfloat16* __restrict__ Bh, const __nv_bfloat16* __restrict__ Bl, size_t ldb,
    int c, int s, uint32_t smaddr, int tid)
{
    uint32_t base = smaddr + s * STAGE_BYTES;
    const __nv_bfloat16* ah = Ah + (size_t)c * BK;
    const __nv_bfloat16* al = Al + (size_t)c * BK;
    const __nv_bfloat16* bh = Bh + (size_t)c * BK;
    const __nv_bfloat16* bl = Bl + (size_t)c * BK;
#pragma unroll
    for (int i = 0; i < 2; i++) {
        int idx = tid + i * 256;
        int r = idx >> 2, cg = (idx & 3) * 4;       // cg: u32 offset in row
        uint32_t doff = (uint32_t)(r * RS32 + cg) * 4;
        cp16(base + doff,             ah + (size_t)r * lda + cg * 2);
        cp16(base + TBYTES   + doff,  al + (size_t)r * lda + cg * 2);
        cp16(base + 2*TBYTES + doff,  bh + (size_t)r * ldb + cg * 2);
        cp16(base + 3*TBYTES + doff,  bl + (size_t)r * ldb + cg * 2);
    }
}

// D[128,128] += A(128 x K) * B(128 x K)^T, K-major bf16 hi/lo, 3-term split.
// Fragment loads via ldmatrix.x4 (conflict-free at 80B row pitch).
__device__ __forceinline__ void mma_mainloop(
    const __nv_bfloat16* __restrict__ Ah, const __nv_bfloat16* __restrict__ Al, size_t lda,
    const __nv_bfloat16* __restrict__ Bh, const __nv_bfloat16* __restrict__ Bl, size_t ldb,
    int nchunks, uint32_t smaddr,
    float acc[2][8][4])
{
    const int tid = threadIdx.x;
    const int lane = tid & 31, wid = tid >> 5;
    const int q = lane >> 3, r = lane & 7;          // ldmatrix quad / row-in-quad
    const int m_base = (wid & 3) * 32;
    const int n_base = (wid >> 2) * 64;

    // per-lane ldmatrix byte offsets within a tile
    const uint32_t aoff = (uint32_t)(m_base + (q & 1) * 8 + r) * RPB + (q >> 1) * 16;
    const uint32_t boff = (uint32_t)(n_base + (q >> 1) * 8 + r) * RPB + (q & 1) * 16;

    if (0 < nchunks) load_chunk(Ah, Al, lda, Bh, Bl, ldb, 0, 0, smaddr, tid);
    CP_COMMIT();

    for (int c = 0; c < nchunks; c++) {
        CP_WAIT0();
        __syncthreads();
        if (c + 1 < nchunks)
            load_chunk(Ah, Al, lda, Bh, Bl, ldb, c + 1, (c + 1) & 1, smaddr, tid);
        CP_COMMIT();

        uint32_t sbase = smaddr + (c & 1) * STAGE_BYTES;
        uint32_t aAh = sbase + aoff;
        uint32_t aBh = sbase + 2*TBYTES + boff;
#pragma unroll
        for (int ks = 0; ks < 2; ks++) {
            uint32_t ah[2][4], al[2][4];
            ldm_x4(ah[0], aAh + ks*32);
            ldm_x4(ah[1], aAh + 1280 + ks*32);            // mf=1: +16 rows * 80B
            ldm_x4(al[0], aAh + TBYTES + ks*32);
            ldm_x4(al[1], aAh + TBYTES + 1280 + ks*32);
#pragma unroll
            for (int p = 0; p < 4; p++) {
                uint32_t bh[4], bl[4];
                ldm_x4(bh, aBh + p*1280 + ks*32);
                ldm_x4(bl, aBh + TBYTES + p*1280 + ks*32);
                float* c0 = acc[0][2*p];   float* c1 = acc[1][2*p];
                float* d0 = acc[0][2*p+1]; float* d1 = acc[1][2*p+1];
                mma_bf16(c0, al[0], bh[0], bh[1]);
                mma_bf16(c1, al[1], bh[0], bh[1]);
                mma_bf16(c0, ah[0], bl[0], bl[1]);
                mma_bf16(c1, ah[1], bl[0], bl[1]);
                mma_bf16(c0, ah[0], bh[0], bh[1]);
                mma_bf16(c1, ah[1], bh[0], bh[1]);
                mma_bf16(d0, al[0], bh[2], bh[3]);
                mma_bf16(d1, al[1], bh[2], bh[3]);
                mma_bf16(d0, ah[0], bl[2], bl[3]);
                mma_bf16(d1, ah[1], bl[2], bl[3]);
                mma_bf16(d0, ah[0], bh[2], bh[3]);
                mma_bf16(d1, ah[1], bh[2], bh[3]);
            }
        }
    }
}

// ============================ split inputs ============================
// which: 0 -> x, 1..3 -> Wq/Wk/Wv
__global__ __launch_bounds__(256) void split_k(const float4* __restrict__ in, int which, int n4)
{
    int i = blockIdx.x * 256 + threadIdx.x;
    if (i >= n4) return;
    __nv_bfloat162* h2; __nv_bfloat162* l2;
    if (which == 0) { h2 = (__nv_bfloat162*)g_xh; l2 = (__nv_bfloat162*)g_xl; }
    else {
        h2 = (__nv_bfloat162*)(g_wh + (size_t)(which - 1) * DD * DD);
        l2 = (__nv_bfloat162*)(g_wl + (size_t)(which - 1) * DD * DD);
    }
    float4 v = in[i];
    __nv_bfloat16 h0, l0, h1, l1;
    bf16split(v.x, h0, l0); bf16split(v.y, h1, l1);
    h2[i*2]   = __nv_bfloat162(h0, h1);
    l2[i*2]   = __nv_bfloat162(l0, l1);
    bf16split(v.z, h0, l0); bf16split(v.w, h1, l1);
    h2[i*2+1] = __nv_bfloat162(h0, h1);
    l2[i*2+1] = __nv_bfloat162(l0, l1);
}

// ============================ kernel 1: QKV ============================
__global__ __launch_bounds__(256, 2) void qkv_k(
    const float* __restrict__ bq, const float* __restrict__ bk, const float* __restrict__ bv)
{
    extern __shared__ uint32_t dsm[];
    uint32_t smaddr = smem_u32(dsm);

    int m0 = blockIdx.x * BM;
    int e0 = blockIdx.y * BN;
    int z = blockIdx.z;
    const float* bias = (z == 0) ? bq : (z == 1) ? bk : bv;

    float acc[2][8][4] = {};
    mma_mainloop(g_xh + (size_t)m0 * DD, g_xl + (size_t)m0 * DD, DD,
                 g_wh + (size_t)z * DD * DD + (size_t)e0 * DD,
                 g_wl + (size_t)z * DD * DD + (size_t)e0 * DD, DD,
                 DD / BK, smaddr, acc);

    int tid = threadIdx.x, lane = tid & 31, wid = tid >> 5;
    int gid = lane >> 2, tig = lane & 3;
    int row0 = m0 + (wid & 3) * 32 + gid;
    int col0 = e0 + (wid >> 2) * 64 + tig * 2;
#pragma unroll
    for (int mf = 0; mf < 2; mf++)
#pragma unroll
    for (int h = 0; h < 2; h++) {
        int row = row0 + mf * 16 + h * 8;
#pragma unroll
        for (int nf = 0; nf < 8; nf++) {
            int col = col0 + nf * 8;
            float y0 = acc[mf][nf][h*2+0] + bias[col];
            float y1 = acc[mf][nf][h*2+1] + bias[col+1];
            size_t off = (size_t)row * DD + col;
            if (z == 2) {
                *(float2*)(g_v + off) = make_float2(y0, y1);
            } else {
                __nv_bfloat16 h0, l0, h1, l1;
                bf16split(y0, h0, l0); bf16split(y1, h1, l1);
                __nv_bfloat16* oh = (z == 0) ? g_qh : g_kh;
                __nv_bfloat16* ol = (z == 0) ? g_ql : g_kl;
                *(__nv_bfloat162*)(oh + off) = __nv_bfloat162(h0, h1);
                *(__nv_bfloat162*)(ol + off) = __nv_bfloat162(l0, l1);
            }
        }
    }
}

// ============================ kernel 2: scores ============================
__global__ __launch_bounds__(256, 2) void scores_k(const int* __restrict__ ev)
{
    int b = blockIdx.z;
    int L = ev[b];
    int q0 = blockIdx.x * BM;
    int k0 = blockIdx.y * BN;
    if (q0 >= L || k0 >= L) return;    // never read downstream

    extern __shared__ uint32_t dsm[];
    uint32_t smaddr = smem_u32(dsm);

    float acc[2][8][4] = {};
    size_t qoff = ((size_t)b * SS + q0) * DD;
    size_t koff = ((size_t)b * SS + k0) * DD;
    mma_mainloop(g_qh + qoff, g_ql + qoff, DD,
                 g_kh + koff, g_kl + koff, DD,
                 DD / BK, smaddr, acc);

    float* P = g_p + (size_t)b * SS * SS;
    int tid = threadIdx.x, lane = tid & 31, wid = tid >> 5;
    int gid = lane >> 2, tig = lane & 3;
    int row0 = q0 + (wid & 3) * 32 + gid;
    int col0 = k0 + (wid >> 2) * 64 + tig * 2;
#pragma unroll
    for (int mf = 0; mf < 2; mf++)
#pragma unroll
    for (int h = 0; h < 2; h++) {
        int q = row0 + mf * 16 + h * 8;
        if (q >= L) continue;
#pragma unroll
        for (int nf = 0; nf < 8; nf++) {
            int k = col0 + nf * 8;
            if (k + 1 < L) {
                float2 v;
                v.x = acc[mf][nf][h*2+0] * SCALEV;
                v.y = acc[mf][nf][h*2+1] * SCALEV;
                *(float2*)(P + (size_t)q * SS + k) = v;
            } else if (k < L) {
                P[(size_t)q * SS + k] = acc[mf][nf][h*2+0] * SCALEV;
            }
        }
    }
}

// ============================ kernel 3: softmax ============================
__global__ __launch_bounds__(256) void softmax_k(const int* __restrict__ ev)
{
    int b = blockIdx.y;
    int q = blockIdx.x;
    int L = ev[b];
    if (q >= L) return;                 // handled via vmean in pv
    size_t off = ((size_t)b * SS + q) * SS;
    const float* row = g_p + off;
    int tid = threadIdx.x;

    float vals[8];
    float m = -3.4e38f;
#pragma unroll
    for (int i = 0; i < 8; i++) {
        int k = tid + i * 256;
        vals[i] = (k < L) ? row[k] : -3.4e38f;
        m = fmaxf(m, vals[i]);
    }
#pragma unroll
    for (int o = 16; o > 0; o >>= 1) m = fmaxf(m, __shfl_xor_sync(0xffffffffu, m, o));
    __shared__ float sred[8];
    if ((tid & 31) == 0) sred[tid >> 5] = m;
    __syncthreads();
    float bm = sred[0];
#pragma unroll
    for (int i = 1; i < 8; i++) bm = fmaxf(bm, sred[i]);
    __syncthreads();

    float s = 0.f;
#pragma unroll
    for (int i = 0; i < 8; i++) {
        int k = tid + i * 256;
        vals[i] = (k < L) ? __expf(vals[i] - bm) : 0.f;
        s += vals[i];
    }
#pragma unroll
    for (int o = 16; o > 0; o >>= 1) s += __shfl_xor_sync(0xffffffffu, s, o);
    if ((tid & 31) == 0) sred[tid >> 5] = s;
    __syncthreads();
    float ts = 0.f;
#pragma unroll
    for (int i = 0; i < 8; i++) ts += sred[i];
    float inv = 1.0f / ts;

#pragma unroll
    for (int i = 0; i < 8; i++) {
        int k = tid + i * 256;
        if (k < L) {
            float p = vals[i] * inv;
            __nv_bfloat16 h, l;
            bf16split(p, h, l);
            g_ph[off + k] = h;
            g_pl[off + k] = l;
        }
    }
    int pad = (L + 31) & ~31;            // zero-fill to BK boundary for pv
    if (pad > SS) pad = SS;
    __nv_bfloat16 z = __float2bfloat16(0.f);
    for (int k = L + tid; k < pad; k += 256) { g_ph[off + k] = z; g_pl[off + k] = z; }
}

// ============================ transpose V -> vT (split) ============================
__global__ void vtrans_k()
{
    __shared__ float t[32][33];
    int b = blockIdx.z;
    int s0 = blockIdx.x * 32;
    int d0 = blockIdx.y * 32;
    int tx = threadIdx.x, ty = threadIdx.y;
    const float* v = g_v + (size_t)b * SS * DD;
#pragma unroll
    for (int i = 0; i < 4; i++)
        t[ty + i*8][tx] = v[(size_t)(s0 + ty + i*8) * DD + d0 + tx];
    __syncthreads();
#pragma unroll
    for (int i = 0; i < 4; i++) {
        float val = t[tx][ty + i*8];
        __nv_bfloat16 h, l;
        bf16split(val, h, l);
        size_t o = (size_t)b * DD * SS + (size_t)(d0 + ty + i*8) * SS + s0 + tx;
        g_vth[o] = h;
        g_vtl[o] = l;
    }
}

// ============================ vmean (deterministic) ============================
__global__ __launch_bounds__(256) void vmean_k()
{
    int b = blockIdx.x;
    int d = blockIdx.y * 256 + threadIdx.x;
    const float* v = g_v + (size_t)b * SS * DD + d;
    float s0 = 0.f, s1 = 0.f, s2 = 0.f, s3 = 0.f;
    for (int s = 0; s < SS; s += 4) {
        s0 += v[(size_t)(s+0) * DD];
        s1 += v[(size_t)(s+1) * DD];
        s2 += v[(size_t)(s+2) * DD];
        s3 += v[(size_t)(s+3) * DD];
    }
    g_vmean[b * DD + d] = (s0 + s1 + s2 + s3) * (1.0f / SS);
}

// ============================ kernel 4: P @ V ============================
__global__ __launch_bounds__(256, 2) void pv_k(const int* __restrict__ ev, float* __restrict__ out)
{
    int b = blockIdx.z;
    int L = ev[b];
    int q0 = blockIdx.x * BM;
    int d0 = blockIdx.y * BN;

    if (q0 >= L) {   // uniform attention -> vmean broadcast
        const float* vm = g_vmean + b * DD + d0;
        for (int idx = threadIdx.x; idx < BM * (BN / 4); idx += 256) {
            int r = idx >> 5, c4 = (idx & 31) * 4;
            float4 v = *(const float4*)(vm + c4);
            *(float4*)(out + ((size_t)(b * SS + q0 + r)) * DD + d0 + c4) = v;
        }
        return;
    }

    extern __shared__ uint32_t dsm[];
    uint32_t smaddr = smem_u32(dsm);

    int pad = (L + 31) & ~31;
    if (pad > SS) pad = SS;
    int nchunks = pad / BK;

    float acc[2][8][4] = {};
    size_t poff = ((size_t)b * SS + q0) * SS;
    size_t voff = ((size_t)b * DD + d0) * SS;
    mma_mainloop(g_ph + poff, g_pl + poff, SS,
                 g_vth + voff, g_vtl + voff, SS,
                 nchunks, smaddr, acc);

    int tid = threadIdx.x, lane = tid & 31, wid = tid >> 5;
    int gid = lane >> 2, tig = lane & 3;
    int row0 = q0 + (wid & 3) * 32 + gid;
    int col0 = d0 + (wid >> 2) * 64 + tig * 2;
    const float* vm = g_vmean + b * DD;
#pragma unroll
    for (int mf = 0; mf < 2; mf++)
#pragma unroll
    for (int h = 0; h < 2; h++) {
        int q = row0 + mf * 16 + h * 8;
        bool qok = q < L;
#pragma unroll
        for (int nf = 0; nf < 8; nf++) {
            int col = col0 + nf * 8;
            float2 v;
            if (qok) { v.x = acc[mf][nf][h*2+0]; v.y = acc[mf][nf][h*2+1]; }
            else     { v.x = vm[col];            v.y = vm[col+1]; }
            *(float2*)(out + (size_t)(b * SS + q) * DD + col) = v;
        }
    }
}

// ============================ launch ============================
extern "C" void kernel_launch(void* const* d_in, const int* in_sizes, int n_in,
                              void* d_out, int out_size)
{
    const float* x  = (const float*)d_in[0];
    const int*   ev = (const int*)  d_in[1];
    const float* Wq = (const float*)d_in[2];
    const float* bq = (const float*)d_in[3];
    const float* Wk = (const float*)d_in[4];
    const float* bk = (const float*)d_in[5];
    const float* Wv = (const float*)d_in[6];
    const float* bv = (const float*)d_in[7];
    float* out = (float*)d_out;

    cudaFuncSetAttribute(qkv_k,    cudaFuncAttributeMaxDynamicSharedMemorySize, SMEM_BYTES);
    cudaFuncSetAttribute(scores_k, cudaFuncAttributeMaxDynamicSharedMemorySize, SMEM_BYTES);
    cudaFuncSetAttribute(pv_k,     cudaFuncAttributeMaxDynamicSharedMemorySize, SMEM_BYTES);

    int nx4 = BB*SS*DD/4, nw4 = DD*DD/4;
    split_k<<<(nx4 + 255)/256, 256>>>((const float4*)x,  0, nx4);
    split_k<<<(nw4 + 255)/256, 256>>>((const float4*)Wq, 1, nw4);
    split_k<<<(nw4 + 255)/256, 256>>>((const float4*)Wk, 2, nw4);
    split_k<<<(nw4 + 255)/256, 256>>>((const float4*)Wv, 3, nw4);

    qkv_k   <<<dim3((BB*SS)/BM, DD/BN, 3), 256, SMEM_BYTES>>>(bq, bk, bv);
    vtrans_k<<<dim3(SS/32, DD/32, BB), dim3(32, 8)>>>();
    vmean_k <<<dim3(BB, DD/256), 256>>>();
    scores_k<<<dim3(SS/BM, SS/BN, BB), 256, SMEM_BYTES>>>(ev);
    softmax_k<<<dim3(SS, BB), 256>>>(ev);
    pv_k    <<<dim3(SS/BM, DD/BN, BB), 256, SMEM_BYTES>>>(ev, out);
}